// round 1
// baseline (speedup 1.0000x reference)
#include <cuda_runtime.h>
#include <cuda_bf16.h>
#include <cstddef>

// Problem constants
constexpr int E    = 4;
constexpr int Bn   = 32;
constexpr int CIN  = 64;
constexpr int H    = 64;
constexpr int W    = 64;
constexpr int COUT = 128;
constexpr int KH   = 3;
constexpr int KW   = 3;
constexpr int HO   = H - KH + 1;  // 62
constexpr int WO   = W - KW + 1;  // 62

// Block: 256 threads.
//   xg = tid & 7   -> x-group, covers x = xg*8 .. xg*8+7   (64 x slots, 62 valid)
//   cg = tid >> 3  -> cout-group, covers j = cg*4 .. cg*4+3 (128 couts)
// Grid: (HO, E*Bn) -> one output row of one (e,b) image per block, all 128 couts.
__global__ __launch_bounds__(256, 4)
void conv_ens3x3_kernel(const float* __restrict__ feat,
                        const float* __restrict__ wgt,
                        const float* __restrict__ bias,
                        float* __restrict__ out)
{
    const int y   = blockIdx.x;        // 0..61
    const int eb  = blockIdx.y;        // 0..127 (e*Bn + b)
    const int e   = eb >> 5;           // Bn = 32
    const int tid = threadIdx.x;
    const int xg  = tid & 7;
    const int cg  = tid >> 3;

    __shared__ float s_in[3][72];          // 3 input rows, 64 data + halo pad
    __shared__ float s_wt[COUT * 9];       // weights for one (e, i): [j][ky*3+kx]

    // Zero the halo region once (never overwritten by the data loads).
    if (tid < 24) {
        s_in[tid / 8][64 + (tid & 7)] = 0.0f;
    }

    float acc[4][8];
#pragma unroll
    for (int cc = 0; cc < 4; cc++)
#pragma unroll
        for (int xx = 0; xx < 8; xx++)
            acc[cc][xx] = 0.0f;

    const float* fbase = feat + (size_t)eb * CIN * H * W;
    const float* wbase = wgt  + (size_t)e  * CIN * COUT * 9;

    const int ldk = tid / 64;   // 0..3  (row selector for input load; only 0..2 used)
    const int ldx = tid & 63;   // 0..63

    for (int i = 0; i < CIN; i++) {
        __syncthreads();

        // --- Stage input: 3 rows x 64 floats (coalesced) ---
        if (tid < 192) {
            s_in[ldk][ldx] = fbase[(size_t)i * H * W + (y + ldk) * W + ldx];
        }

        // --- Stage weights: 128 couts x 9 taps = 1152 contiguous floats ---
        {
            const float4* wsrc = reinterpret_cast<const float4*>(wbase + (size_t)i * COUT * 9);
            float4*       wdst = reinterpret_cast<float4*>(s_wt);
            // 1152/4 = 288 float4
            if (tid < 288) wdst[tid] = wsrc[tid];
            int k2 = tid + 256;
            if (k2 < 288) wdst[k2] = wsrc[k2];
        }

        __syncthreads();

        // --- Compute: 4 couts x 8 x x 9 taps = 288 FMA per thread per i ---
#pragma unroll
        for (int ky = 0; ky < 3; ky++) {
            float rin[10];
#pragma unroll
            for (int u = 0; u < 10; u++)
                rin[u] = s_in[ky][xg * 8 + u];

#pragma unroll
            for (int cc = 0; cc < 4; cc++) {
                const int j = cg * 4 + cc;
                const float w0 = s_wt[j * 9 + ky * 3 + 0];
                const float w1 = s_wt[j * 9 + ky * 3 + 1];
                const float w2 = s_wt[j * 9 + ky * 3 + 2];
#pragma unroll
                for (int xx = 0; xx < 8; xx++) {
                    acc[cc][xx] = fmaf(rin[xx + 0], w0, acc[cc][xx]);
                    acc[cc][xx] = fmaf(rin[xx + 1], w1, acc[cc][xx]);
                    acc[cc][xx] = fmaf(rin[xx + 2], w2, acc[cc][xx]);
                }
            }
        }
    }

    // --- Epilogue: add bias, store (guard x < WO) ---
#pragma unroll
    for (int cc = 0; cc < 4; cc++) {
        const int j  = cg * 4 + cc;
        const float bv = bias[e * COUT + j];
        float* orow = out + (((size_t)eb * COUT + j) * HO + y) * WO;
#pragma unroll
        for (int xx = 0; xx < 8; xx++) {
            const int x = xg * 8 + xx;
            if (x < WO) {
                orow[x] = acc[cc][xx] + bv;
            }
        }
    }
}

extern "C" void kernel_launch(void* const* d_in, const int* in_sizes, int n_in,
                              void* d_out, int out_size)
{
    const float* feat = (const float*)d_in[0];   // (E, B, C_in, H, W)
    const float* wgt  = (const float*)d_in[1];   // (E, C_in, C_out, 3, 3)
    const float* bias = (const float*)d_in[2];   // (E, C_out)
    float*       out  = (float*)d_out;           // (E, B, C_out, 62, 62)

    dim3 grid(HO, E * Bn);
    conv_ens3x3_kernel<<<grid, 256>>>(feat, wgt, bias, out);
}

// round 4
// speedup vs baseline: 5.1771x; 5.1771x over previous
#include <cuda_runtime.h>
#include <cuda_bf16.h>
#include <cstdint>
#include <cstddef>

// ---------------- problem constants ----------------
constexpr int E    = 4;
constexpr int Bn   = 32;
constexpr int CIN  = 64;
constexpr int H    = 64;
constexpr int W    = 64;
constexpr int COUT = 128;
constexpr int HO   = 62;
constexpr int WO   = 62;
constexpr int NTAPS = 9;

// ---------------- SMEM layout (byte offsets) ----------------
// fp32 stage: 64 ch x 257-float pitch (256 pos + 1 pad)
constexpr int SM_STAGE = 0;                      // 65792 B
// G: transposed features [264 pos][64 ch] bf16, 128B rows, 16B-chunk XOR swizzle
constexpr int SM_GHI  = 65792;                   // 33792 B
constexpr int SM_GLO  = 99584;                   // 33792 B
// Weights: 2 buffers x (hi 18432 + lo 18432); row j: 72 bf16 slots (144B pitch)
constexpr int SM_W    = 133376;                  // 73728 B
constexpr int SM_BIAS = 207104;                  // 512 B
constexpr int SM_TOTAL = 207616;

constexpr int WBLK = 36864;   // bytes per (e,tap): hi 18432 | lo 18432

// ---------------- prepped weights ----------------
__device__ __align__(16) unsigned char g_wprep[E * NTAPS * WBLK];

__global__ void prep_weights_kernel(const float* __restrict__ wgt) {
    int idx = blockIdx.x * blockDim.x + threadIdx.x;
    if (idx >= E * NTAPS * COUT * CIN) return;
    int i    = idx & 63;          // input channel = k index
    int j    = (idx >> 6) & 127;  // cout = m index
    int rest = idx >> 13;
    int tap  = rest % NTAPS;
    int e    = rest / NTAPS;

    float v = wgt[(((size_t)e * CIN + i) * COUT + j) * 9 + tap];
    __nv_bfloat16 h = __float2bfloat16(v);
    __nv_bfloat16 l = __float2bfloat16(v - __bfloat162float(h));

    size_t base = (size_t)(e * NTAPS + tap) * WBLK;
    *(__nv_bfloat16*)(g_wprep + base +         (size_t)j * 144 + i * 2) = h;
    *(__nv_bfloat16*)(g_wprep + base + 18432 + (size_t)j * 144 + i * 2) = l;
}

// ---------------- PTX helpers (all plain sm_80-class, no 'a' features) ----------------
__device__ __forceinline__ uint32_t smem_u32(const void* p) {
    uint32_t a;
    asm("{ .reg .u64 t; cvta.to.shared.u64 t, %1; cvt.u32.u64 %0, t; }" : "=r"(a) : "l"(p));
    return a;
}
__device__ __forceinline__ void cpasync16(uint32_t dst, const void* src) {
    asm volatile("cp.async.cg.shared.global [%0], [%1], 16;" :: "r"(dst), "l"(src));
}
__device__ __forceinline__ void cpasync_commit() {
    asm volatile("cp.async.commit_group;" ::: "memory");
}
__device__ __forceinline__ void cpasync_wait0() {
    asm volatile("cp.async.wait_group 0;" ::: "memory");
}
__device__ __forceinline__ void ldsm_x4(uint32_t& r0, uint32_t& r1, uint32_t& r2, uint32_t& r3,
                                        uint32_t addr) {
    asm volatile("ldmatrix.sync.aligned.m8n8.x4.shared.b16 {%0,%1,%2,%3}, [%4];"
                 : "=r"(r0), "=r"(r1), "=r"(r2), "=r"(r3) : "r"(addr));
}
__device__ __forceinline__ void mma16816(float* c, const uint32_t* a, uint32_t b0, uint32_t b1) {
    asm volatile(
        "mma.sync.aligned.m16n8k16.row.col.f32.bf16.bf16.f32 "
        "{%0,%1,%2,%3}, {%4,%5,%6,%7}, {%8,%9}, {%0,%1,%2,%3};"
        : "+f"(c[0]), "+f"(c[1]), "+f"(c[2]), "+f"(c[3])
        : "r"(a[0]), "r"(a[1]), "r"(a[2]), "r"(a[3]), "r"(b0), "r"(b1));
}

// ---------------- main kernel ----------------
// Block: 256 threads (8 warps). Warp wid: jbase=(wid&1)*64 (couts), pbase=(wid>>1)*32 (pos).
// Per warp: 4 m16 tiles x 4 n8 tiles, K=576 = 9 taps x 4 k16 steps, x3 hi/lo terms.
__global__ __launch_bounds__(256)
void conv_hmma_kernel(const float* __restrict__ feat,
                      const float* __restrict__ bias,
                      float* __restrict__ out)
{
    extern __shared__ __align__(128) char smem[];
    const int tid  = threadIdx.x;
    const int wid  = tid >> 5;
    const int lane = tid & 31;
    const int eb   = blockIdx.y;
    const int e    = eb >> 5;
    const int y0   = blockIdx.x * 2;
    const uint32_t sb = smem_u32(smem);

    // --- 1) async-copy weights for tap 0 into buffer 0 (overlaps staging) ---
    {
        const unsigned char* src = g_wprep + (size_t)(e * NTAPS) * WBLK;
        uint32_t dst = sb + SM_W;
#pragma unroll
        for (int c = 0; c < 9; c++) {
            int off = (c * 256 + tid) * 16;
            cpasync16(dst + off, src + off);
        }
        cpasync_commit();
    }

    // --- 2) stage fp32 features: 64 ch x 4 rows x 64 x, pitch 257 floats ---
    {
        const float* fb = feat + (size_t)eb * CIN * H * W + (size_t)y0 * W;
        float* sf = (float*)(smem + SM_STAGE);
#pragma unroll
        for (int c = 0; c < 64; c++) {
            int idx = c * 256 + tid;
            int i = idx >> 8, rx = idx & 255;
            sf[i * 257 + rx] = fb[(size_t)i * (H * W) + rx];
        }
        if (tid < COUT) ((float*)(smem + SM_BIAS))[tid] = bias[e * COUT + tid];
    }
    __syncthreads();

    // --- 3) build G[pos][ch] bf16 hi/lo (128B rows, 16B-chunk XOR swizzle), zero pad rows ---
    {
        if (tid < 128) {
            ((uint2*)(smem + SM_GHI + 256 * 128))[tid] = make_uint2(0u, 0u);
            ((uint2*)(smem + SM_GLO + 256 * 128))[tid] = make_uint2(0u, 0u);
        }
        const float* sf = (const float*)(smem + SM_STAGE);
        const int c2 = 2 * lane;           // channel pair (c2, c2+1)
#pragma unroll
        for (int it = 0; it < 32; it++) {
            const int p = wid * 32 + it;   // pos 0..255
            float v0 = sf[c2 * 257 + p];
            float v1 = sf[(c2 + 1) * 257 + p];
            __nv_bfloat162 hp = __floats2bfloat162_rn(v0, v1);   // .x=ch c2 (low), .y=c2+1
            float2 hf = __bfloat1622float2(hp);
            __nv_bfloat162 lp = __floats2bfloat162_rn(v0 - hf.x, v1 - hf.y);
            uint32_t boff = (uint32_t)p * 128 + (uint32_t)(((lane >> 2) ^ (p & 7)) << 4)
                          + (uint32_t)(lane & 3) * 4;
            *(__nv_bfloat162*)(smem + SM_GHI + boff) = hp;
            *(__nv_bfloat162*)(smem + SM_GLO + boff) = lp;
        }
    }
    cpasync_wait0();
    __syncthreads();

    // --- 4) main loop over 9 taps ---
    const int jbase = (wid & 1) * 64;
    const int pbase = (wid >> 1) * 32;
    const int tt = lane >> 3, r = lane & 7;
    // A (weights) ldmatrix per-lane offset: tiles (m+,k+) laid as reg order a0..a3
    const uint32_t aoff = (uint32_t)(((tt & 1) * 8 + r) * 144 + (tt >> 1) * 16);
    // B (features) per-lane row/chunk parts
    const int br  = (tt >> 1) * 8 + r;
    const int kcb = tt & 1;

    float acc[4][4][4];
#pragma unroll
    for (int a = 0; a < 4; a++)
#pragma unroll
        for (int b = 0; b < 4; b++)
#pragma unroll
            for (int c = 0; c < 4; c++) acc[a][b][c] = 0.0f;

    for (int t = 0; t < NTAPS; t++) {
        const int buf = t & 1;
        if (t < NTAPS - 1) {
            const unsigned char* src = g_wprep + (size_t)(e * NTAPS + t + 1) * WBLK;
            uint32_t dst = sb + SM_W + (buf ^ 1) * WBLK;
#pragma unroll
            for (int c = 0; c < 9; c++) {
                int off = (c * 256 + tid) * 16;
                cpasync16(dst + off, src + off);
            }
            cpasync_commit();
        }

        const int ky = t / 3, kx = t - ky * 3;
        const int pshift = pbase + ky * 64 + kx;
        const uint32_t whi = sb + SM_W + (uint32_t)buf * WBLK;
        const uint32_t wlo = whi + 18432;

#pragma unroll
        for (int kq = 0; kq < 4; kq++) {
            const int k0 = kq * 16;
            uint32_t ah[4][4], al[4][4];
#pragma unroll
            for (int mt = 0; mt < 4; mt++) {
                uint32_t abase = (uint32_t)((jbase + mt * 16) * 144 + k0 * 2) + aoff;
                ldsm_x4(ah[mt][0], ah[mt][1], ah[mt][2], ah[mt][3], whi + abase);
                ldsm_x4(al[mt][0], al[mt][1], al[mt][2], al[mt][3], wlo + abase);
            }
#pragma unroll
            for (int nt = 0; nt < 2; nt++) {
                const int P  = pshift + nt * 16 + br;
                const int kc = (k0 >> 3) + kcb;
                const uint32_t gb = (uint32_t)P * 128 + (uint32_t)((kc ^ (P & 7)) << 4);
                uint32_t bh[4], bl[4];
                ldsm_x4(bh[0], bh[1], bh[2], bh[3], sb + SM_GHI + gb);
                ldsm_x4(bl[0], bl[1], bl[2], bl[3], sb + SM_GLO + gb);
#pragma unroll
                for (int mt = 0; mt < 4; mt++) {
#pragma unroll
                    for (int sub = 0; sub < 2; sub++) {
                        float* c = acc[mt][nt * 2 + sub];
                        mma16816(c, ah[mt], bh[2 * sub], bh[2 * sub + 1]);
                        mma16816(c, al[mt], bh[2 * sub], bh[2 * sub + 1]);
                        mma16816(c, ah[mt], bl[2 * sub], bl[2 * sub + 1]);
                    }
                }
            }
        }

        if (t < NTAPS - 1) cpasync_wait0();
        __syncthreads();
    }

    // --- 5) epilogue: bias + coalesced-ish float2 stores (32B segments per j-row) ---
    const float* sbias = (const float*)(smem + SM_BIAS);
#pragma unroll
    for (int mt = 0; mt < 4; mt++) {
        const int j0 = jbase + mt * 16 + (lane >> 2);
        const float b0 = sbias[j0];
        const float b1 = sbias[j0 + 8];
#pragma unroll
        for (int q = 0; q < 4; q++) {
            const int pos = pbase + q * 8 + 2 * (lane & 3);
            const int x = pos & 63;
            const int y = y0 + (pos >> 6);
            if (x < WO) {
                float2 v0 = make_float2(acc[mt][q][0] + b0, acc[mt][q][1] + b0);
                float2 v1 = make_float2(acc[mt][q][2] + b1, acc[mt][q][3] + b1);
                *(float2*)(out + (((size_t)eb * COUT + j0)     * HO + y) * WO + x) = v0;
                *(float2*)(out + (((size_t)eb * COUT + j0 + 8) * HO + y) * WO + x) = v1;
            }
        }
    }
}

// ---------------- launch ----------------
extern "C" void kernel_launch(void* const* d_in, const int* in_sizes, int n_in,
                              void* d_out, int out_size)
{
    const float* feat = (const float*)d_in[0];  // (E, B, C_in, H, W)
    const float* wgt  = (const float*)d_in[1];  // (E, C_in, C_out, 3, 3)
    const float* bias = (const float*)d_in[2];  // (E, C_out)
    float*       out  = (float*)d_out;          // (E, B, C_out, 62, 62)

    static bool attr_set = false;
    cudaFuncSetAttribute(conv_hmma_kernel,
                         cudaFuncAttributeMaxDynamicSharedMemorySize, SM_TOTAL);
    (void)attr_set;

    const int total = E * NTAPS * COUT * CIN;
    prep_weights_kernel<<<(total + 255) / 256, 256>>>(wgt);

    dim3 grid(HO / 2, E * Bn);  // (31, 128)
    conv_hmma_kernel<<<grid, 256, SM_TOTAL>>>(feat, bias, out);
}

// round 6
// speedup vs baseline: 6.1994x; 1.1975x over previous
#include <cuda_runtime.h>
#include <cuda_bf16.h>
#include <cstdint>
#include <cstddef>

// ---------------- problem constants ----------------
constexpr int E    = 4;
constexpr int Bn   = 32;
constexpr int CIN  = 64;
constexpr int H    = 64;
constexpr int W    = 64;
constexpr int COUT = 128;
constexpr int HO   = 62;
constexpr int WO   = 62;
constexpr int NTAPS = 9;

// ---------------- SMEM layout (byte offsets) ----------------
// G: transposed features [264 pos][64 ch] bf16, 128B rows, 16B-chunk XOR swizzle
constexpr int SM_GHI   = 0;          // 33792 B (264 rows x 128 B)
constexpr int SM_GLO   = 33792;      // 33792 B
// UNION region: fp32 stage chunk (32 ch x 257 floats = 32896 B) OR weight tile
constexpr int SM_STAGE = 67584;      // 32896 B  (prologue only)
constexpr int SM_W     = 67584;      // 36864 B  (hi 18432 | lo 18432)
constexpr int SM_BIAS  = 104448;     // 512 B
constexpr int SM_TOTAL = 104960;     // 2 blocks/SM: 209920 <= 228KB

constexpr int WBLK = 36864;   // bytes per (e,tap): hi 18432 | lo 18432 (144B row pitch)

// ---------------- prepped weights ----------------
__device__ __align__(16) unsigned char g_wprep[E * NTAPS * WBLK];

__global__ void prep_weights_kernel(const float* __restrict__ wgt) {
    int idx = blockIdx.x * blockDim.x + threadIdx.x;
    if (idx >= E * NTAPS * COUT * CIN) return;
    int i    = idx & 63;          // input channel = k index
    int j    = (idx >> 6) & 127;  // cout = m index
    int rest = idx >> 13;
    int tap  = rest % NTAPS;
    int e    = rest / NTAPS;

    float v = wgt[(((size_t)e * CIN + i) * COUT + j) * 9 + tap];
    __nv_bfloat16 h = __float2bfloat16(v);
    __nv_bfloat16 l = __float2bfloat16(v - __bfloat162float(h));

    size_t base = (size_t)(e * NTAPS + tap) * WBLK;
    *(__nv_bfloat16*)(g_wprep + base +         (size_t)j * 144 + i * 2) = h;
    *(__nv_bfloat16*)(g_wprep + base + 18432 + (size_t)j * 144 + i * 2) = l;
}

// ---------------- PTX helpers (plain sm_80-class; no 'a' features) ----------------
__device__ __forceinline__ uint32_t smem_u32(const void* p) {
    uint32_t a;
    asm("{ .reg .u64 t; cvta.to.shared.u64 t, %1; cvt.u32.u64 %0, t; }" : "=r"(a) : "l"(p));
    return a;
}
__device__ __forceinline__ void cpasync16(uint32_t dst, const void* src) {
    asm volatile("cp.async.cg.shared.global [%0], [%1], 16;" :: "r"(dst), "l"(src));
}
__device__ __forceinline__ void cpasync_commit() {
    asm volatile("cp.async.commit_group;" ::: "memory");
}
__device__ __forceinline__ void cpasync_wait0() {
    asm volatile("cp.async.wait_group 0;" ::: "memory");
}
__device__ __forceinline__ void ldsm_x4(uint32_t& r0, uint32_t& r1, uint32_t& r2, uint32_t& r3,
                                        uint32_t addr) {
    asm volatile("ldmatrix.sync.aligned.m8n8.x4.shared.b16 {%0,%1,%2,%3}, [%4];"
                 : "=r"(r0), "=r"(r1), "=r"(r2), "=r"(r3) : "r"(addr));
}
__device__ __forceinline__ void mma16816(float* c, const uint32_t* a, uint32_t b0, uint32_t b1) {
    asm volatile(
        "mma.sync.aligned.m16n8k16.row.col.f32.bf16.bf16.f32 "
        "{%0,%1,%2,%3}, {%4,%5,%6,%7}, {%8,%9}, {%0,%1,%2,%3};"
        : "+f"(c[0]), "+f"(c[1]), "+f"(c[2]), "+f"(c[3])
        : "r"(a[0]), "r"(a[1]), "r"(a[2]), "r"(a[3]), "r"(b0), "r"(b1));
}

// ---------------- main kernel ----------------
// 256 threads (8 warps). Warp wid: jbase=(wid&1)*64 (couts), pbase=(wid>>1)*32 (pos).
// Per warp: 4 m16 x 4 n8 tiles; K=576 = 9 taps x 4 k16, x3 hi/lo terms.
__global__ __launch_bounds__(256, 2)
void conv_hmma_kernel(const float* __restrict__ feat,
                      const float* __restrict__ bias,
                      float* __restrict__ out)
{
    extern __shared__ __align__(128) char smem[];
    const int tid  = threadIdx.x;
    const int wid  = tid >> 5;
    const int lane = tid & 31;
    const int eb   = blockIdx.y;
    const int e    = eb >> 5;
    const int y0   = blockIdx.x * 2;
    const uint32_t sb = smem_u32(smem);

    // --- 0) zero G pad rows (256..263), load bias ---
    if (tid < 128) {
        ((uint2*)(smem + SM_GHI + 256 * 128))[tid] = make_uint2(0u, 0u);
        ((uint2*)(smem + SM_GLO + 256 * 128))[tid] = make_uint2(0u, 0u);
        ((float*)(smem + SM_BIAS))[tid] = bias[e * COUT + tid];
    }

    // --- 1) stage + transpose features in two 32-channel chunks ---
    const float* fb = feat + (size_t)eb * CIN * H * W + (size_t)y0 * W;
    float* sf = (float*)(smem + SM_STAGE);
#pragma unroll
    for (int q = 0; q < 2; q++) {
        __syncthreads();   // protect stage buffer (and, for q=0, pad-zero order)
        // load 32 channels x 4 rows x 64 x (coalesced)
#pragma unroll
        for (int c = 0; c < 32; c++) {
            int idx = c * 256 + tid;
            int i = idx >> 8, rx = idx & 255;
            sf[i * 257 + rx] = fb[(size_t)(q * 32 + i) * (H * W) + rx];
        }
        __syncthreads();
        // build G[p][ch] bf16 hi/lo: warp = pos group, lane = channel (in chunk)
        const int ch   = q * 32 + lane;
        const int chnk = (ch * 2) >> 4;           // 16B chunk index within row
        const int cin16 = (ch * 2) & 15;          // byte within chunk
#pragma unroll
        for (int it = 0; it < 32; it++) {
            const int p = wid * 32 + it;
            float v = sf[lane * 257 + p];
            __nv_bfloat16 h = __float2bfloat16(v);
            __nv_bfloat16 l = __float2bfloat16(v - __bfloat162float(h));
            uint32_t boff = (uint32_t)p * 128 + (uint32_t)((chnk ^ (p & 7)) << 4) + cin16;
            *(__nv_bfloat16*)(smem + SM_GHI + boff) = h;
            *(__nv_bfloat16*)(smem + SM_GLO + boff) = l;
        }
    }
    __syncthreads();   // stage dead; union region may now hold weights

    // --- 2) copy weights for tap 0 ---
    {
        const unsigned char* src = g_wprep + (size_t)(e * NTAPS) * WBLK;
#pragma unroll
        for (int c = 0; c < 9; c++) {
            int off = (c * 256 + tid) * 16;
            cpasync16(sb + SM_W + off, src + off);
        }
        cpasync_commit();
        cpasync_wait0();
    }
    __syncthreads();

    // --- 3) main loop over 9 taps ---
    const int jbase = (wid & 1) * 64;
    const int pbase = (wid >> 1) * 32;
    const int tt = lane >> 3, r = lane & 7;
    const uint32_t aoff = (uint32_t)(((tt & 1) * 8 + r) * 144 + (tt >> 1) * 16);
    const int br  = (tt >> 1) * 8 + r;
    const int kcb = tt & 1;

    float acc[4][4][4];
#pragma unroll
    for (int a = 0; a < 4; a++)
#pragma unroll
        for (int b = 0; b < 4; b++)
#pragma unroll
            for (int c = 0; c < 4; c++) acc[a][b][c] = 0.0f;

    const uint32_t whi = sb + SM_W;
    const uint32_t wlo = whi + 18432;

    for (int t = 0; t < NTAPS; t++) {
        const int ky = t / 3, kx = t - ky * 3;
        const int pshift = pbase + ky * 64 + kx;

#pragma unroll
        for (int kq = 0; kq < 4; kq++) {
            const int k0 = kq * 16;
            uint32_t ah[4][4], al[4][4];
#pragma unroll
            for (int mt = 0; mt < 4; mt++) {
                uint32_t abase = (uint32_t)((jbase + mt * 16) * 144 + k0 * 2) + aoff;
                ldsm_x4(ah[mt][0], ah[mt][1], ah[mt][2], ah[mt][3], whi + abase);
                ldsm_x4(al[mt][0], al[mt][1], al[mt][2], al[mt][3], wlo + abase);
            }
#pragma unroll
            for (int nt = 0; nt < 2; nt++) {
                const int P  = pshift + nt * 16 + br;
                const int kc = (k0 >> 3) + kcb;
                const uint32_t gb = (uint32_t)P * 128 + (uint32_t)((kc ^ (P & 7)) << 4);
                uint32_t bh[4], bl[4];
                ldsm_x4(bh[0], bh[1], bh[2], bh[3], sb + SM_GHI + gb);
                ldsm_x4(bl[0], bl[1], bl[2], bl[3], sb + SM_GLO + gb);
#pragma unroll
                for (int mt = 0; mt < 4; mt++) {
#pragma unroll
                    for (int sub = 0; sub < 2; sub++) {
                        float* c = acc[mt][nt * 2 + sub];
                        mma16816(c, ah[mt], bh[2 * sub], bh[2 * sub + 1]);
                        mma16816(c, al[mt], bh[2 * sub], bh[2 * sub + 1]);
                        mma16816(c, ah[mt], bl[2 * sub], bl[2 * sub + 1]);
                    }
                }
            }
        }

        // single-buffer weight swap: all warps done reading W, then overwrite
        if (t < NTAPS - 1) {
            __syncthreads();
            const unsigned char* src = g_wprep + (size_t)(e * NTAPS + t + 1) * WBLK;
#pragma unroll
            for (int c = 0; c < 9; c++) {
                int off = (c * 256 + tid) * 16;
                cpasync16(sb + SM_W + off, src + off);
            }
            cpasync_commit();
            cpasync_wait0();
            __syncthreads();
        }
    }

    // --- 4) epilogue: bias + float2 stores ---
    const float* sbias = (const float*)(smem + SM_BIAS);
#pragma unroll
    for (int mt = 0; mt < 4; mt++) {
        const int j0 = jbase + mt * 16 + (lane >> 2);
        const float b0 = sbias[j0];
        const float b1 = sbias[j0 + 8];
#pragma unroll
        for (int q = 0; q < 4; q++) {
            const int pos = pbase + q * 8 + 2 * (lane & 3);
            const int x = pos & 63;
            const int y = y0 + (pos >> 6);
            if (x < WO) {
                float2 v0 = make_float2(acc[mt][q][0] + b0, acc[mt][q][1] + b0);
                float2 v1 = make_float2(acc[mt][q][2] + b1, acc[mt][q][3] + b1);
                *(float2*)(out + (((size_t)eb * COUT + j0)     * HO + y) * WO + x) = v0;
                *(float2*)(out + (((size_t)eb * COUT + j0 + 8) * HO + y) * WO + x) = v1;
            }
        }
    }
}

// ---------------- launch ----------------
extern "C" void kernel_launch(void* const* d_in, const int* in_sizes, int n_in,
                              void* d_out, int out_size)
{
    const float* feat = (const float*)d_in[0];  // (E, B, C_in, H, W)
    const float* wgt  = (const float*)d_in[1];  // (E, C_in, C_out, 3, 3)
    const float* bias = (const float*)d_in[2];  // (E, C_out)
    float*       out  = (float*)d_out;          // (E, B, C_out, 62, 62)

    cudaFuncSetAttribute(conv_hmma_kernel,
                         cudaFuncAttributeMaxDynamicSharedMemorySize, SM_TOTAL);

    const int total = E * NTAPS * COUT * CIN;
    prep_weights_kernel<<<(total + 255) / 256, 256>>>(wgt);

    dim3 grid(HO / 2, E * Bn);  // (31, 128)
    conv_hmma_kernel<<<grid, 256, SM_TOTAL>>>(feat, bias, out);
}